// round 3
// baseline (speedup 1.0000x reference)
#include <cuda_runtime.h>
#include <math.h>

// ---------------------------------------------------------------------------
// Categorical 2D semantic map: 16 frames, trilinear splat -> round -> z-sum.
//
// Pipeline per kernel_launch (graph-capturable, allocation-free):
//   1) scatter_kernel: one thread per (frame, downsampled pixel). Computes the
//      8 trilinear corners and atomicAdds weights into __device__ scratch.
//      Channel 0 needs all 80 z-levels; sem channels only z in [8,25).
//   2) reduce_kernel: per (frame, x, y) sums rintf(voxel) over z, clips, writes
//      output, and zeroes every nonzero cell it touched (scratch stays clean
//      across graph replays -> no memset pass needed).
// ---------------------------------------------------------------------------

#define H2 120          // 480 / 4
#define W2 160          // 640 / 4
#define VR 100          // VISION_RANGE
#define ZL 80           // Z_LEVELS
#define ZAG_LO 8        // MIN_MAPPED_H
#define ZAG_HI 25       // MAX_MAPPED_H
#define ZAG_N  17
#define NSEM 16
#define NFRAMES 16
#define CH_ELEMS (480 * 640)
#define FRAME_ELEMS (20 * CH_ELEMS)

// Scratch accumulators (zero-initialized at module load; reduce_kernel
// restores them to zero every call).
__device__ float g_c0[NFRAMES * ZL * VR * VR];                        // [f][z][x][y]
__device__ float g_sem[(size_t)NFRAMES * NSEM * ZAG_N * VR * VR];     // [f][c][zr][x][y]

__global__ void __launch_bounds__(W2) scatter_kernel(const float* __restrict__ obs,
                                                     const float f_pix) {
    const int j = threadIdx.x;   // 0..159 (downsampled col)
    const int i = blockIdx.x;    // 0..119 (downsampled row)
    const int f = blockIdx.y;    // frame

    const float* frame = obs + (size_t)f * FRAME_ELEMS;
    const float Yd = __ldg(frame + 3 * CH_ELEMS + (4 * i) * 640 + 4 * j);
    if (!(Yd > 20.0f && Yd < 500.0f)) return;

    // Replicate the exact float op sequence of the reference (matters only at
    // rintf half-way ties, but it's free).
    const float X  = ((float)(4 * j) - 319.5f) * Yd / f_pix;
    const float Z  = (239.5f - (float)(4 * i)) * Yd / f_pix;
    const float xm = X + 250.0f;
    const float zm = Z + 88.0f;
    const float xn = (xm / 5.0f - 50.0f) / 100.0f * 2.0f;
    const float yn = (Yd / 5.0f - 50.0f) / 100.0f * 2.0f;
    const float zn = (zm / 5.0f - 32.0f) / 80.0f * 2.0f;
    const float posx = xn * 50.0f + 50.0f;
    const float posy = yn * 50.0f + 50.0f;
    const float posz = zn * 40.0f + 40.0f;

    const float bxf = floorf(posx), byf = floorf(posy), bzf = floorf(posz);
    float wx[2], wy[2], wz[2];
#pragma unroll
    for (int t = 0; t < 2; t++) {
        float p;
        p = bxf + (float)t; wx[t] = (p > 0.0f && p < (float)VR) ? (1.0f - fabsf(posx - p)) : 0.0f;
        p = byf + (float)t; wy[t] = (p > 0.0f && p < (float)VR) ? (1.0f - fabsf(posy - p)) : 0.0f;
        p = bzf + (float)t; wz[t] = (p > 0.0f && p < (float)ZL) ? (1.0f - fabsf(posz - p)) : 0.0f;
    }
    if ((wx[0] == 0.0f && wx[1] == 0.0f) ||
        (wy[0] == 0.0f && wy[1] == 0.0f) ||
        (wz[0] == 0.0f && wz[1] == 0.0f)) return;

    const int xb = (int)bxf, yb = (int)byf, zb = (int)bzf;

    // --- channel 0 (occupancy): all z levels ---
    float* c0f = g_c0 + f * (ZL * VR * VR);
    bool semz[2];
#pragma unroll
    for (int tz = 0; tz < 2; tz++) {
        semz[tz] = false;
        if (wz[tz] == 0.0f) continue;
        const int z = zb + tz;
        semz[tz] = (z >= ZAG_LO && z < ZAG_HI);
        float* plane = c0f + z * (VR * VR);
#pragma unroll
        for (int tx = 0; tx < 2; tx++) {
            if (wx[tx] == 0.0f) continue;
#pragma unroll
            for (int ty = 0; ty < 2; ty++) {
                const float w = (wx[tx] * wy[ty]) * wz[tz];
                if (w > 0.0f) atomicAdd(plane + (xb + tx) * VR + (yb + ty), w);
            }
        }
    }

    // Sem channels contribute to the output only via z in [8,25): skip the
    // expensive 1KB pooled load if no corner lands there.
    if (!(semz[0] || semz[1])) return;

    // 4x4 average pool of the 16 semantic channels at this pixel.
    float sem[NSEM];
    const float* sbase = frame + 4 * CH_ELEMS + (4 * i) * 640 + 4 * j;
#pragma unroll
    for (int c = 0; c < NSEM; c++) {
        const float* cp = sbase + c * CH_ELEMS;
        float s = 0.0f;
#pragma unroll
        for (int r = 0; r < 4; r++) {
            float4 v = *reinterpret_cast<const float4*>(cp + r * 640);
            s += v.x + v.y + v.z + v.w;
        }
        sem[c] = s * 0.0625f;
    }

    float* semf = g_sem + (size_t)f * (NSEM * ZAG_N * VR * VR);
#pragma unroll
    for (int tz = 0; tz < 2; tz++) {
        if (!semz[tz]) continue;
        const int zr = zb + tz - ZAG_LO;
#pragma unroll
        for (int tx = 0; tx < 2; tx++) {
            if (wx[tx] == 0.0f) continue;
#pragma unroll
            for (int ty = 0; ty < 2; ty++) {
                const float w = (wx[tx] * wy[ty]) * wz[tz];
                if (w <= 0.0f) continue;
                float* cell = semf + zr * (VR * VR) + (xb + tx) * VR + (yb + ty);
#pragma unroll
                for (int c = 0; c < NSEM; c++)
                    atomicAdd(cell + c * (ZAG_N * VR * VR), sem[c] * w);
            }
        }
    }
}

// grid = (x=100, group=17, frame=16), block = 100 threads (y).
// group 0 -> channel-0 occupancy (80 z), groups 1..16 -> sem channel g-1 (17 z).
// Loads are fully coalesced: adjacent y threads hit adjacent addresses, z is
// the strided (slow) scratch dimension.
__global__ void __launch_bounds__(VR) reduce_kernel(float* __restrict__ out) {
    const int y = threadIdx.x;
    const int x = blockIdx.x;
    const int g = blockIdx.y;
    const int f = blockIdx.z;

    if (g == 0) {
        float* base = g_c0 + f * (ZL * VR * VR) + x * VR + y;
        float s_all = 0.0f, s_ag = 0.0f;
#pragma unroll
        for (int z = 0; z < ZL; z++) {
            const float v = base[z * (VR * VR)];
            if (v != 0.0f) {
                base[z * (VR * VR)] = 0.0f;         // restore scratch for next replay
                const float r = rintf(v);            // jnp.round = half-to-even
                s_all += r;
                if (z >= ZAG_LO && z < ZAG_HI) s_ag += r;
            }
        }
        float* o = out + (size_t)(f * 18) * (VR * VR) + x * VR + y;
        o[0]       = fminf(fmaxf(s_ag,  0.0f), 1.0f);   // fp_map   (/1.0)
        o[VR * VR] = fminf(fmaxf(s_all, 0.0f), 1.0f);   // fp_exp   (/1.0)
    } else {
        const int c = g - 1;
        float* base = g_sem + ((size_t)f * NSEM + c) * (ZAG_N * VR * VR) + x * VR + y;
        float s = 0.0f;
#pragma unroll
        for (int z = 0; z < ZAG_N; z++) {
            const float v = base[z * (VR * VR)];
            if (v != 0.0f) {
                base[z * (VR * VR)] = 0.0f;
                s += rintf(v);
            }
        }
        out[((size_t)f * 18 + 2 + c) * (VR * VR) + x * VR + y] =
            fminf(fmaxf(s / 5.0f, 0.0f), 1.0f);         // sem_map (/5.0)
    }
}

extern "C" void kernel_launch(void* const* d_in, const int* in_sizes, int n_in,
                              void* d_out, int out_size) {
    const float* obs = (const float*)d_in[0];
    float* out = (float*)d_out;
    (void)in_sizes; (void)n_in; (void)out_size;

    // F_PIX computed in double (as numpy does), then narrowed to float32.
    const float f_pix = (float)(320.0 / tan(39.5 * 3.14159265358979323846 / 180.0));

    scatter_kernel<<<dim3(H2, NFRAMES), W2>>>(obs, f_pix);
    reduce_kernel<<<dim3(VR, ZAG_N, NFRAMES), VR>>>(out);
}